// round 4
// baseline (speedup 1.0000x reference)
#include <cuda_runtime.h>

#define Nn   50000
#define Ee   600000
#define IND  384
#define HIDD 128
#define HYPD 256

// ---------------- scratch (static device globals; no runtime allocation) ----------------
__device__ __align__(128) float g_xemb[(size_t)Nn * HIDD];
__device__ __align__(128) float g_cur [(size_t)Nn * HIDD];
__device__ __align__(128) float g_nxt [(size_t)Nn * HIDD];
__device__ __align__(128) float g_acc [(size_t)Nn * HIDD];
__device__ __align__(128) float g_Hm  [(size_t)Nn * HYPD];
__device__ __align__(128) float g_lat [HYPD * HIDD];
__device__ __align__(128) int   g_deg [Nn];
__device__ __align__(128) float g_dinv[Nn];
__device__ __align__(128) int   g_rowptr[Nn + 1];
__device__ __align__(128) int   g_fill[Nn];
__device__ __align__(128) int   g_col [Ee];
__device__ __align__(128) float g_val [Ee];
__device__ __align__(128) int   g_bsum[256];

// ---------------- init: zero deg / fill / lat ----------------
__global__ void init_k() {
    int i = blockIdx.x * blockDim.x + threadIdx.x;
    if (i < Nn) { g_deg[i] = 0; g_fill[i] = 0; }
    if (i < HYPD * HIDD) g_lat[i] = 0.f;
}

// ---------------- degree count ----------------
__global__ void deg_k(const int* __restrict__ dst) {
    int e = blockIdx.x * blockDim.x + threadIdx.x;
    if (e < Ee) atomicAdd(&g_deg[dst[e]], 1);
}

__global__ void dinv_k() {
    int i = blockIdx.x * blockDim.x + threadIdx.x;
    if (i < Nn) {
        int d = g_deg[i];
        g_dinv[i] = (d > 0) ? rsqrtf((float)d) : 0.f;
    }
}

// ---------------- 3-kernel exclusive scan over g_deg -> g_rowptr ----------------
__global__ void scan1_k() {
    __shared__ int sm[256];
    int t = threadIdx.x;
    int i = blockIdx.x * 256 + t;
    int v = (i < Nn) ? g_deg[i] : 0;
    sm[t] = v;
    __syncthreads();
    #pragma unroll
    for (int o = 1; o < 256; o <<= 1) {
        int add = (t >= o) ? sm[t - o] : 0;
        __syncthreads();
        sm[t] += add;
        __syncthreads();
    }
    if (i < Nn) g_rowptr[i] = sm[t] - v;        // exclusive within block
    if (t == 255) g_bsum[blockIdx.x] = sm[255]; // block total
}

__global__ void scan2_k(int nb) {
    if (threadIdx.x == 0 && blockIdx.x == 0) {
        int run = 0;
        for (int b = 0; b < nb; b++) { int tmp = g_bsum[b]; g_bsum[b] = run; run += tmp; }
    }
}

__global__ void scan3_k() {
    int i = blockIdx.x * blockDim.x + threadIdx.x;
    if (i < Nn) g_rowptr[i] += g_bsum[i >> 8];
    if (i == 0) g_rowptr[Nn] = Ee;
}

// ---------------- CSR fill (+ edge weights) ----------------
__global__ void fill_k(const int* __restrict__ src, const int* __restrict__ dst) {
    int e = blockIdx.x * blockDim.x + threadIdx.x;
    if (e >= Ee) return;
    int s = src[e], d = dst[e];
    int p = g_rowptr[d] + atomicAdd(&g_fill[d], 1);
    g_col[p] = s;
    g_val[p] = g_dinv[s] * g_dinv[d];
}

// ---------------- generic fp32 SGEMM: C[M,N] = A[M,K] @ B[K,N] (+bias, relu) ----------------
// BM=128, BN=128, BK=16, 256 threads, 8x8 register tile. K must be a multiple of 16,
// N a multiple of 128 (covered by gridDim.y). M guarded.
__global__ __launch_bounds__(256) void sgemm_k(
    const float* __restrict__ A, const float* __restrict__ B,
    const float* __restrict__ bias, float* __restrict__ C,
    float* __restrict__ C2, int M, int N, int K, int relu)
{
    __shared__ float As[16][128];   // transposed: As[k][row]
    __shared__ float Bs[16][128];   // natural:    Bs[k][col]
    const int tid = threadIdx.x;
    const int tr = tid >> 4, tc = tid & 15;
    const int rowBase = blockIdx.x * 128;
    const int colBase = blockIdx.y * 128;

    float acc[8][8];
    #pragma unroll
    for (int i = 0; i < 8; i++)
        #pragma unroll
        for (int j = 0; j < 8; j++) acc[i][j] = 0.f;

    for (int k0 = 0; k0 < K; k0 += 16) {
        #pragma unroll
        for (int q = 0; q < 2; q++) {              // A tile: 128x16 -> transposed
            int f = tid * 2 + q;
            int r = f >> 2, c4 = f & 3;
            int grow = rowBase + r;
            float4 v = make_float4(0.f, 0.f, 0.f, 0.f);
            if (grow < M) v = *(const float4*)(A + (size_t)grow * K + k0 + c4 * 4);
            As[c4 * 4 + 0][r] = v.x; As[c4 * 4 + 1][r] = v.y;
            As[c4 * 4 + 2][r] = v.z; As[c4 * 4 + 3][r] = v.w;
        }
        #pragma unroll
        for (int q = 0; q < 2; q++) {              // B tile: 16x128
            int f = tid * 2 + q;
            int r = f >> 5, c4 = f & 31;
            *(float4*)(&Bs[r][c4 * 4]) =
                *(const float4*)(B + (size_t)(k0 + r) * N + colBase + c4 * 4);
        }
        __syncthreads();
        #pragma unroll
        for (int k = 0; k < 16; k++) {
            float ra[8], rb[8];
            *(float4*)(ra)     = *(const float4*)(&As[k][tr * 8]);
            *(float4*)(ra + 4) = *(const float4*)(&As[k][tr * 8 + 4]);
            *(float4*)(rb)     = *(const float4*)(&Bs[k][tc * 8]);
            *(float4*)(rb + 4) = *(const float4*)(&Bs[k][tc * 8 + 4]);
            #pragma unroll
            for (int i = 0; i < 8; i++)
                #pragma unroll
                for (int j = 0; j < 8; j++)
                    acc[i][j] += ra[i] * rb[j];
        }
        __syncthreads();
    }

    float bj[8];
    #pragma unroll
    for (int j = 0; j < 8; j++) bj[j] = bias ? bias[colBase + tc * 8 + j] : 0.f;

    #pragma unroll
    for (int i = 0; i < 8; i++) {
        int grow = rowBase + tr * 8 + i;
        if (grow >= M) continue;
        float v[8];
        #pragma unroll
        for (int j = 0; j < 8; j++) {
            float t = acc[i][j] + bj[j];
            v[j] = relu ? fmaxf(t, 0.f) : t;
        }
        float* cp = C + (size_t)grow * N + colBase + tc * 8;
        *(float4*)cp       = *(float4*)v;
        *(float4*)(cp + 4) = *(float4*)(v + 4);
        if (C2) {
            float* c2p = C2 + (size_t)grow * N + colBase + tc * 8;
            *(float4*)c2p       = *(float4*)v;
            *(float4*)(c2p + 4) = *(float4*)(v + 4);
        }
    }
}

// ---------------- gumbel-softmax over HYP=256 (warp per row, in-place on g_Hm) ----------------
__global__ void softmax_k(const float* __restrict__ gum) {
    int row  = (blockIdx.x * blockDim.x + threadIdx.x) >> 5;
    int lane = threadIdx.x & 31;
    if (row >= Nn) return;
    const float* lrow = g_Hm + (size_t)row * HYPD;
    const float* urow = gum  + (size_t)row * HYPD;
    float t[8];
    #pragma unroll
    for (int q = 0; q < 2; q++) {
        float4 lg = *(const float4*)(lrow + lane * 8 + q * 4);
        float4 uu = *(const float4*)(urow + lane * 8 + q * 4);
        // (logit + gumbel)/tau, tau=0.5; gumbel = -log(-log(u+eps)+eps)
        t[q*4+0] = (lg.x - logf(-logf(uu.x + 1e-10f) + 1e-10f)) * 2.f;
        t[q*4+1] = (lg.y - logf(-logf(uu.y + 1e-10f) + 1e-10f)) * 2.f;
        t[q*4+2] = (lg.z - logf(-logf(uu.z + 1e-10f) + 1e-10f)) * 2.f;
        t[q*4+3] = (lg.w - logf(-logf(uu.w + 1e-10f) + 1e-10f)) * 2.f;
    }
    float m = t[0];
    #pragma unroll
    for (int j = 1; j < 8; j++) m = fmaxf(m, t[j]);
    #pragma unroll
    for (int o = 16; o; o >>= 1) m = fmaxf(m, __shfl_xor_sync(0xffffffffu, m, o));
    float s = 0.f;
    #pragma unroll
    for (int j = 0; j < 8; j++) { t[j] = expf(t[j] - m); s += t[j]; }
    #pragma unroll
    for (int o = 16; o; o >>= 1) s += __shfl_xor_sync(0xffffffffu, s, o);
    float inv = 1.f / s;
    float* orow = g_Hm + (size_t)row * HYPD;
    #pragma unroll
    for (int q = 0; q < 2; q++) {
        float4 v = make_float4(t[q*4+0]*inv, t[q*4+1]*inv, t[q*4+2]*inv, t[q*4+3]*inv);
        *(float4*)(orow + lane * 8 + q * 4) = v;
    }
}

// ---------------- LightGCN propagation: warp per dst row, CSR gather ----------------
__global__ void prop_k(const float* __restrict__ cur, float* __restrict__ nxt) {
    int row  = (blockIdx.x * blockDim.x + threadIdx.x) >> 5;
    int lane = threadIdx.x & 31;
    if (row >= Nn) return;
    int s = g_rowptr[row], e = g_rowptr[row + 1];
    float4 a = make_float4(0.f, 0.f, 0.f, 0.f);
    for (int p = s; p < e; p++) {
        float w = g_val[p];
        int   c = g_col[p];
        float4 v = *(const float4*)(cur + (size_t)c * HIDD + lane * 4);
        a.x += w * v.x; a.y += w * v.y; a.z += w * v.z; a.w += w * v.w;
    }
    size_t off = (size_t)row * HIDD + lane * 4;
    *(float4*)(nxt + off) = a;
    float4 ac = *(float4*)(g_acc + off);
    ac.x += a.x; ac.y += a.y; ac.z += a.z; ac.w += a.w;
    *(float4*)(g_acc + off) = ac;
}

// ---------------- lat[HYP,HID] = Hm^T @ x_emb (split over N, atomic reduce) ----------------
__global__ __launch_bounds__(256) void lat_k(const float* __restrict__ Hm,
                                             const float* __restrict__ Xe, int splits) {
    __shared__ float Hs[16][64];
    __shared__ float Xs[16][128];
    int hypBase = blockIdx.x * 64;
    int nPer = (Nn + splits - 1) / splits;
    int n0 = blockIdx.y * nPer;
    int n1 = min(n0 + nPer, Nn);
    int tid = threadIdx.x;
    int th = tid >> 4, tc = tid & 15;   // th: 16 groups of 4 hyp ; tc: 16 groups of 8 cols
    float acc[4][8];
    #pragma unroll
    for (int a = 0; a < 4; a++)
        #pragma unroll
        for (int b = 0; b < 8; b++) acc[a][b] = 0.f;

    for (int nb = n0; nb < n1; nb += 16) {
        {
            int r = tid >> 4, c4 = tid & 15;
            int n = nb + r;
            float4 v = make_float4(0.f, 0.f, 0.f, 0.f);
            if (n < n1) v = *(const float4*)(Hm + (size_t)n * HYPD + hypBase + c4 * 4);
            *(float4*)(&Hs[r][c4 * 4]) = v;
        }
        #pragma unroll
        for (int q = 0; q < 2; q++) {
            int f = tid * 2 + q;
            int r = f >> 5, c4 = f & 31;
            int n = nb + r;
            float4 v = make_float4(0.f, 0.f, 0.f, 0.f);
            if (n < n1) v = *(const float4*)(Xe + (size_t)n * HIDD + c4 * 4);
            *(float4*)(&Xs[r][c4 * 4]) = v;
        }
        __syncthreads();
        #pragma unroll
        for (int k = 0; k < 16; k++) {
            float rh[4], rx[8];
            *(float4*)rh       = *(const float4*)(&Hs[k][th * 4]);
            *(float4*)rx       = *(const float4*)(&Xs[k][tc * 8]);
            *(float4*)(rx + 4) = *(const float4*)(&Xs[k][tc * 8 + 4]);
            #pragma unroll
            for (int a = 0; a < 4; a++)
                #pragma unroll
                for (int b = 0; b < 8; b++)
                    acc[a][b] += rh[a] * rx[b];
        }
        __syncthreads();
    }
    #pragma unroll
    for (int a = 0; a < 4; a++)
        #pragma unroll
        for (int b = 0; b < 8; b++)
            atomicAdd(&g_lat[(size_t)(hypBase + th * 4 + a) * HIDD + tc * 8 + b], acc[a][b]);
}

// ---------------- final = acc/4 + alpha * hyper/||hyper||  (warp per row) ----------------
__global__ void final_k(float* __restrict__ out) {
    int row  = (blockIdx.x * blockDim.x + threadIdx.x) >> 5;
    int lane = threadIdx.x & 31;
    if (row >= Nn) return;
    size_t off = (size_t)row * HIDD + lane * 4;
    float4 h = *(const float4*)(g_nxt + off);   // hyper_out lives in g_nxt
    float ss = h.x * h.x + h.y * h.y + h.z * h.z + h.w * h.w;
    #pragma unroll
    for (int o = 16; o; o >>= 1) ss += __shfl_xor_sync(0xffffffffu, ss, o);
    float inv = 0.1f / fmaxf(sqrtf(ss), 1e-12f);
    float4 a = *(const float4*)(g_acc + off);
    float4 r;
    r.x = a.x * 0.25f + h.x * inv;
    r.y = a.y * 0.25f + h.y * inv;
    r.z = a.z * 0.25f + h.z * inv;
    r.w = a.w * 0.25f + h.w * inv;
    *(float4*)(out + off) = r;
}

// ---------------- launcher ----------------
extern "C" void kernel_launch(void* const* d_in, const int* in_sizes, int n_in,
                              void* d_out, int out_size) {
    const float* x       = (const float*)d_in[0];
    const int*   ei      = (const int*)  d_in[1];
    const float* gum     = (const float*)d_in[2];
    const float* w_feat  = (const float*)d_in[3];
    const float* b_feat  = (const float*)d_in[4];
    const float* w_hyper = (const float*)d_in[5];
    const float* w_vis   = (const float*)d_in[6];
    const float* b_vis   = (const float*)d_in[7];
    const float* w_txt   = (const float*)d_in[8];
    const float* b_txt   = (const float*)d_in[9];
    float* out = (float*)d_out;
    const int* src = ei;
    const int* dst = ei + Ee;

    float *xemb, *cur, *nxt, *acc, *Hm, *lat;
    cudaGetSymbolAddress((void**)&xemb, g_xemb);
    cudaGetSymbolAddress((void**)&cur,  g_cur);
    cudaGetSymbolAddress((void**)&nxt,  g_nxt);
    cudaGetSymbolAddress((void**)&acc,  g_acc);
    cudaGetSymbolAddress((void**)&Hm,   g_Hm);
    cudaGetSymbolAddress((void**)&lat,  g_lat);

    const int NB   = (Nn + 255) / 256;      // 196
    const int EB   = (Ee + 255) / 256;      // 2344
    const int MB   = (Nn + 127) / 128;      // 391
    const int WB   = (Nn * 32 + 255) / 256; // 6250  (warp-per-row kernels)
    const int SPLITS = 64;

    // ---- graph normalization + CSR build ----
    init_k <<<NB, 256>>>();
    deg_k  <<<EB, 256>>>(dst);
    dinv_k <<<NB, 256>>>();
    scan1_k<<<NB, 256>>>();
    scan2_k<<<1, 32>>>(NB);
    scan3_k<<<NB, 256>>>();
    fill_k <<<EB, 256>>>(src, dst);

    // ---- x_emb = x @ w_feat + b_feat   (also initializes acc = x_emb) ----
    sgemm_k<<<dim3(MB, 1), 256>>>(x, w_feat, b_feat, xemb, acc, Nn, HIDD, IND, 0);

    // ---- logits = x_emb @ w_hyper  -> g_Hm, then in-place gumbel-softmax ----
    sgemm_k<<<dim3(MB, 2), 256>>>(xemb, w_hyper, nullptr, Hm, nullptr, Nn, HYPD, HIDD, 0);
    softmax_k<<<WB, 256>>>(gum);

    // ---- LightGCN: 3 propagation layers, acc accumulates ----
    prop_k<<<WB, 256>>>(xemb, cur);
    prop_k<<<WB, 256>>>(cur, nxt);
    prop_k<<<WB, 256>>>(nxt, cur);

    // ---- lat = Hm^T @ x_emb ; hyper_out = Hm @ lat (into g_nxt, free after layer 3) ----
    lat_k<<<dim3(4, SPLITS), 256>>>(Hm, xemb, SPLITS);
    sgemm_k<<<dim3(MB, 1), 256>>>(Hm, lat, nullptr, nxt, nullptr, Nn, HIDD, HYPD, 0);

    // ---- final = acc/4 + alpha*normalize(hyper) -> out[0 : N*HID] ----
    final_k<<<WB, 256>>>(out);

    // ---- x_vision / x_text ----
    sgemm_k<<<dim3(MB, 1), 256>>>(out, w_vis, b_vis, out + (size_t)Nn * HIDD,     nullptr, Nn, HIDD, HIDD, 1);
    sgemm_k<<<dim3(MB, 1), 256>>>(out, w_txt, b_txt, out + (size_t)2 * Nn * HIDD, nullptr, Nn, HIDD, HIDD, 1);
}